// round 4
// baseline (speedup 1.0000x reference)
#include <cuda_runtime.h>
#include <cuda_bf16.h>
#include <cstdint>

// ---------------------------------------------------------------------------
// Constants
// ---------------------------------------------------------------------------
constexpr int NROWS = 8192;
constexpr int DDIM  = 256;
constexpr int BM    = 128;            // Q rows per CTA
constexpr int BN    = 64;             // G rows per tile
constexpr int NTU   = 8;              // tiles per CTA (unit)
constexpr int NCHUNK = NROWS / (BN * NTU);    // 16 column chunks
constexpr int GRID_F = (NROWS / BM) * NCHUNK; // 1024 CTAs
constexpr int ROWB  = DDIM * 2;       // 512 bytes per bf16 row
constexpr int TILE_BYTES = BN * ROWB; // 32768
constexpr int A_BYTES = BM * ROWB;    // 65536
constexpr int NBUF  = 4;

constexpr int SM_A    = 0;
constexpr int SM_G    = A_BYTES;                     // 65536
constexpr int SM_MBAR = SM_G + NBUF * TILE_BYTES;    // 196608
constexpr int SMEM_TOTAL = SM_MBAR + 64;

#define LOG2E 1.4426950408889634f

// ---------------------------------------------------------------------------
// Device scratch
// ---------------------------------------------------------------------------
__device__ __align__(128) unsigned char g_swz[NROWS * ROWB];  // 4 MB G bf16 (swizzled)
__device__ __align__(128) unsigned char q_swz[NROWS * ROWB];  // 4 MB Q bf16*log2e (swizzled)
__device__ float g_diag_arr[NROWS];                           // diag * log2e (exact fp32)
__device__ float g_ps[NCHUNK * NROWS];
__device__ unsigned g_cnt = 0;

// ---------------------------------------------------------------------------
// PTX helpers (sm_103 baseline only)
// ---------------------------------------------------------------------------
__device__ __forceinline__ uint32_t smem_to_u32(const void* p) {
    uint32_t a;
    asm("{ .reg .u64 t; cvta.to.shared.u64 t, %1; cvt.u32.u64 %0, t; }" : "=r"(a) : "l"(p));
    return a;
}

__device__ __forceinline__ float ex2(float x) {
    float r;
    asm("ex2.approx.f32 %0, %1;" : "=f"(r) : "f"(x));
    return r;
}

#define MBARRIER_INIT(addr, count) \
    asm volatile("mbarrier.init.shared.b64 [%0], %1;" :: "r"((uint32_t)(addr)), "r"((uint32_t)(count)) : "memory")

#define MBARRIER_EXPECT_TX(addr, tx) \
    asm volatile("mbarrier.arrive.expect_tx.shared.b64 _, [%0], %1;" :: "r"((uint32_t)(addr)), "r"((uint32_t)(tx)) : "memory")

#define MBARRIER_WAIT_PARITY(addr, ph) do { \
    uint32_t _m = (uint32_t)(addr), _p = (uint32_t)(ph), _d; \
    asm volatile("{\n\t.reg .pred p;\n\t" \
        "mbarrier.try_wait.parity.acquire.cta.shared::cta.b64 p, [%1], %2;\n\t" \
        "selp.b32 %0, 1, 0, p;\n\t}" : "=r"(_d) : "r"(_m), "r"(_p) : "memory"); \
    if (!_d) { \
        asm volatile("{\n\t.reg .pred P1;\n\t" \
            "WL_%=:\n\t" \
            "mbarrier.try_wait.parity.acquire.cta.shared::cta.b64 P1, [%0], %1, 0x989680;\n\t" \
            "@P1 bra.uni WD_%=;\n\t" \
            "bra.uni WL_%=;\n\t" \
            "WD_%=:\n\t}" :: "r"(_m), "r"(_p) : "memory"); \
    } \
} while (0)

__device__ __forceinline__ void bulk_g2s(uint32_t dst, const void* src, uint32_t bytes, uint32_t mbar) {
    asm volatile(
        "cp.async.bulk.shared::cluster.global.mbarrier::complete_tx::bytes [%0], [%1], %2, [%3];"
        :: "r"(dst), "l"(src), "r"(bytes), "r"(mbar) : "memory");
}

__device__ __forceinline__ void ldsm_x4(uint32_t& r0, uint32_t& r1, uint32_t& r2, uint32_t& r3,
                                        uint32_t addr) {
    asm volatile("ldmatrix.sync.aligned.m8n8.x4.shared.b16 {%0,%1,%2,%3}, [%4];"
        : "=r"(r0), "=r"(r1), "=r"(r2), "=r"(r3) : "r"(addr));
}

__device__ __forceinline__ void mma_bf16(float* c, uint32_t a0, uint32_t a1, uint32_t a2, uint32_t a3,
                                         uint32_t b0, uint32_t b1) {
    asm volatile(
        "mma.sync.aligned.m16n8k16.row.col.f32.bf16.bf16.f32 "
        "{%0,%1,%2,%3}, {%4,%5,%6,%7}, {%8,%9}, {%0,%1,%2,%3};"
        : "+f"(c[0]), "+f"(c[1]), "+f"(c[2]), "+f"(c[3])
        : "r"(a0), "r"(a1), "r"(a2), "r"(a3), "r"(b0), "r"(b1));
}

__device__ __forceinline__ uint32_t pack_bf16(float lo, float hi) {
    uint32_t r;
    asm("cvt.rn.bf16x2.f32 %0, %1, %2;" : "=r"(r) : "f"(hi), "f"(lo));
    return r;
}

// ---------------------------------------------------------------------------
// Prep: [0,1024) G->bf16 swz; [1024,2048) Q->bf16*log2e swz; [2048,3072) diag
// ---------------------------------------------------------------------------
__global__ void prep_kernel(const float* __restrict__ q, const float* __restrict__ g) {
    if (blockIdx.x < 2048) {
        bool isQ = blockIdx.x >= 1024;
        const float* src = isQ ? q : g;
        unsigned char* dst = isQ ? q_swz : g_swz;
        float scale = isQ ? LOG2E : 1.0f;
        int idx = (blockIdx.x & 1023) * 256 + threadIdx.x;   // 16B bf16 chunk (8 floats)
        int j = idx >> 5;          // row
        int c = idx & 31;          // chunk16 within row
        const float4* s4 = reinterpret_cast<const float4*>(src);
        float4 v0 = s4[j * 64 + c * 2];
        float4 v1 = s4[j * 64 + c * 2 + 1];
        uint4 u;
        u.x = pack_bf16(v0.x * scale, v0.y * scale);
        u.y = pack_bf16(v0.z * scale, v0.w * scale);
        u.z = pack_bf16(v1.x * scale, v1.y * scale);
        u.w = pack_bf16(v1.z * scale, v1.w * scale);
        int blk = j >> 6, r = j & 63;   // 64-row blocks for both planes
        *reinterpret_cast<uint4*>(dst + (size_t)blk * TILE_BYTES + r * ROWB +
                                  ((c ^ (r & 7)) << 4)) = u;
    } else {
        int w = threadIdx.x >> 5, lane = threadIdx.x & 31;
        int row = (blockIdx.x - 2048) * 8 + w;
        const float4* qr = reinterpret_cast<const float4*>(q + (size_t)row * DDIM);
        const float4* gr = reinterpret_cast<const float4*>(g + (size_t)row * DDIM);
        float acc = 0.f;
#pragma unroll
        for (int i = 0; i < 2; i++) {
            float4 a = qr[i * 32 + lane];
            float4 b = gr[i * 32 + lane];
            acc += a.x * b.x + a.y * b.y + a.z * b.z + a.w * b.w;
        }
#pragma unroll
        for (int o = 16; o; o >>= 1) acc += __shfl_xor_sync(0xffffffffu, acc, o);
        if (lane == 0) g_diag_arr[row] = acc * LOG2E;
    }
}

// ---------------------------------------------------------------------------
// Main fused kernel (no-max base-2 softmax, bulk-copied A, last-CTA finalize)
// ---------------------------------------------------------------------------
__global__ void __launch_bounds__(256, 1)
fused_kernel(float* __restrict__ out) {
    extern __shared__ char smem[];
    const uint32_t sb = smem_to_u32(smem);
    const int tid  = threadIdx.x;
    const int wid  = tid >> 5;
    const int lane = tid & 31;
    const int rb    = blockIdx.x >> 4;    // row block (0..63)
    const int chunk = blockIdx.x & 15;    // column chunk (0..15)
    const int ct0   = chunk * NTU;
    const uint32_t mbarA = sb + SM_MBAR + NBUF * 8;

    if (tid == 0) {
#pragma unroll
        for (int i = 0; i <= NBUF; i++) MBARRIER_INIT(sb + SM_MBAR + i * 8, 1);
    }
    asm volatile("fence.proxy.async.shared::cta;" ::: "memory");
    __syncthreads();

    if (tid == 0) {
        // A: two 64-row blocks of q_swz -> smem (contiguous: rb*2, rb*2+1)
        MBARRIER_EXPECT_TX(mbarA, A_BYTES);
        bulk_g2s(sb + SM_A, q_swz + (size_t)rb * A_BYTES, A_BYTES, mbarA);
#pragma unroll
        for (int p = 0; p < NBUF; p++) {
            MBARRIER_EXPECT_TX(sb + SM_MBAR + p * 8, TILE_BYTES);
            bulk_g2s(sb + SM_G + p * TILE_BYTES,
                     g_swz + (size_t)(ct0 + p) * TILE_BYTES,
                     TILE_BYTES, sb + SM_MBAR + p * 8);
        }
    }

    // ---- per-lane addressing ----
    const int g_row = lane >> 2;
    const uint32_t a_row  = wid * 16 + ((lane >> 3) & 1) * 8 + (lane & 7);
    const uint32_t a_base = sb + SM_A + a_row * ROWB;
    const uint32_t a_x    = a_row & 7;
    const uint32_t a_hi   = lane >> 4;
    const uint32_t b_rowl = ((lane >> 4) << 3) + (lane & 7);
    const uint32_t b_x    = b_rowl & 7;
    const uint32_t b_hi   = (lane >> 3) & 1;
    const uint32_t b_roff = b_rowl * ROWB;

    float sA = 0.f, sB = 0.f;
    float acc[32];

    MBARRIER_WAIT_PARITY(mbarA, 0);   // A resident

#pragma unroll 1
    for (int t = 0; t < NTU; t++) {
        const int b = t & (NBUF - 1);
        const uint32_t mb = sb + SM_MBAR + b * 8;
        MBARRIER_WAIT_PARITY(mb, (t >> 2) & 1);
#pragma unroll
        for (int i = 0; i < 32; i++) acc[i] = 0.f;
        const uint32_t gbase = sb + SM_G + b * TILE_BYTES + b_roff;
#pragma unroll
        for (int ks = 0; ks < 16; ks++) {
            uint32_t a0, a1, a2, a3;
            ldsm_x4(a0, a1, a2, a3, a_base + ((((ks << 1) + a_hi) ^ a_x) << 4));
            const uint32_t bc = (((ks << 1) + b_hi) ^ b_x) << 4;
#pragma unroll
            for (int nb = 0; nb < 4; nb++) {
                uint32_t b0, b1, b2, b3;
                ldsm_x4(b0, b1, b2, b3, gbase + nb * (16 * ROWB) + bc);
                mma_bf16(acc + nb * 8 + 0, a0, a1, a2, a3, b0, b1);
                mma_bf16(acc + nb * 8 + 4, a0, a1, a2, a3, b2, b3);
            }
        }
        __syncthreads();   // all warps done reading buf b
        if (tid == 0 && t + NBUF < NTU) {
            MBARRIER_EXPECT_TX(mb, TILE_BYTES);
            bulk_g2s(sb + SM_G + b * TILE_BYTES,
                     g_swz + (size_t)(ct0 + t + NBUF) * TILE_BYTES,
                     TILE_BYTES, mb);
        }
        // ---- epilogue: plain sum of 2^logit (no max tracking) ----
        float t0 = 0.f, t1 = 0.f;
#pragma unroll
        for (int i = 0; i < 8; i++) {
            t0 += ex2(acc[i * 4 + 0]) + ex2(acc[i * 4 + 1]);
            t1 += ex2(acc[i * 4 + 2]) + ex2(acc[i * 4 + 3]);
        }
        sA += t0; sB += t1;
    }

    // ---- quad reduce (lanes sharing a row) + write partial sums ----
    sA += __shfl_xor_sync(0xffffffffu, sA, 1);
    sA += __shfl_xor_sync(0xffffffffu, sA, 2);
    sB += __shfl_xor_sync(0xffffffffu, sB, 1);
    sB += __shfl_xor_sync(0xffffffffu, sB, 2);
    if ((lane & 3) == 0) {
        int r0 = rb * BM + wid * 16 + g_row;
        g_ps[chunk * NROWS + r0] = sA;
        g_ps[chunk * NROWS + r0 + 8] = sB;
    }

    // ---- last-CTA finalize ----
    __shared__ unsigned s_last;
    __shared__ float red[256];
    __threadfence();
    __syncthreads();
    if (tid == 0) {
        unsigned old = atomicAdd(&g_cnt, 1u);
        s_last = (old == GRID_F - 1) ? 1u : 0u;
        if (s_last) g_cnt = 0;   // reset for next replay
    }
    __syncthreads();
    if (!s_last) return;
    __threadfence();

    float acc2 = 0.f;
    for (int i = tid; i < NROWS; i += 256) {
        float S = 0.f;
#pragma unroll
        for (int c = 0; c < NCHUNK; c++) S += g_ps[c * NROWS + i];
        float p = ex2(g_diag_arr[i]) / S;
        acc2 += -logf(p + 1e-5f);
    }
    red[tid] = acc2;
    __syncthreads();
    for (int o = 128; o; o >>= 1) {
        if (tid < o) red[tid] += red[tid + o];
        __syncthreads();
    }
    if (tid == 0) out[0] = red[0] / (float)NROWS;
}

// ---------------------------------------------------------------------------
// Launch
// ---------------------------------------------------------------------------
extern "C" void kernel_launch(void* const* d_in, const int* in_sizes, int n_in,
                              void* d_out, int out_size) {
    (void)in_sizes; (void)n_in; (void)out_size;
    const float* q = (const float*)d_in[0];
    const float* g = (const float*)d_in[1];
    float* out = (float*)d_out;

    cudaFuncSetAttribute(fused_kernel, cudaFuncAttributeMaxDynamicSharedMemorySize, SMEM_TOTAL);

    prep_kernel<<<3072, 256>>>(q, g);
    fused_kernel<<<GRID_F, 256, SMEM_TOTAL>>>(out);
}

// round 5
// speedup vs baseline: 1.4832x; 1.4832x over previous
#include <cuda_runtime.h>
#include <cuda_bf16.h>
#include <cstdint>

// ---------------------------------------------------------------------------
// Constants
// ---------------------------------------------------------------------------
constexpr int NROWS = 8192;
constexpr int DDIM  = 256;
constexpr int BM    = 128;            // Q rows per CTA
constexpr int BN    = 64;             // G rows per tile
constexpr int NTU   = 8;              // tiles per CTA (unit)
constexpr int NCHUNK = NROWS / (BN * NTU);    // 16 column chunks
constexpr int GRID_F = (NROWS / BM) * NCHUNK; // 1024 CTAs
constexpr int ROWB  = DDIM * 2;       // 512 bytes per bf16 row
constexpr int TILE_BYTES = BN * ROWB; // 32768
constexpr int A_BYTES = BM * ROWB;    // 65536
constexpr int NBUF  = 4;

constexpr int SM_A    = 0;
constexpr int SM_G    = A_BYTES;                     // 65536
constexpr int SM_MBAR = SM_G + NBUF * TILE_BYTES;    // 196608
constexpr int SMEM_TOTAL = SM_MBAR + 64;

#define LOG2E 1.4426950408889634f

// ---------------------------------------------------------------------------
// Device scratch
// ---------------------------------------------------------------------------
__device__ __align__(128) unsigned char g_swz[NROWS * ROWB];  // 4 MB G bf16 (swizzled)
__device__ __align__(128) unsigned char q_swz[NROWS * ROWB];  // 4 MB Q bf16*log2e (swizzled)
__device__ float g_diag_arr[NROWS];                           // diag * log2e (exact fp32)
__device__ float g_ps[NCHUNK * NROWS];
__device__ unsigned g_cnt = 0;

// ---------------------------------------------------------------------------
// PTX helpers (sm_103 baseline only)
// ---------------------------------------------------------------------------
__device__ __forceinline__ uint32_t smem_to_u32(const void* p) {
    uint32_t a;
    asm("{ .reg .u64 t; cvta.to.shared.u64 t, %1; cvt.u32.u64 %0, t; }" : "=r"(a) : "l"(p));
    return a;
}

__device__ __forceinline__ float ex2(float x) {
    float r;
    asm("ex2.approx.f32 %0, %1;" : "=f"(r) : "f"(x));
    return r;
}

#define MBARRIER_INIT(addr, count) \
    asm volatile("mbarrier.init.shared.b64 [%0], %1;" :: "r"((uint32_t)(addr)), "r"((uint32_t)(count)) : "memory")

#define MBARRIER_EXPECT_TX(addr, tx) \
    asm volatile("mbarrier.arrive.expect_tx.shared.b64 _, [%0], %1;" :: "r"((uint32_t)(addr)), "r"((uint32_t)(tx)) : "memory")

#define MBARRIER_WAIT_PARITY(addr, ph) do { \
    uint32_t _m = (uint32_t)(addr), _p = (uint32_t)(ph), _d; \
    asm volatile("{\n\t.reg .pred p;\n\t" \
        "mbarrier.try_wait.parity.acquire.cta.shared::cta.b64 p, [%1], %2;\n\t" \
        "selp.b32 %0, 1, 0, p;\n\t}" : "=r"(_d) : "r"(_m), "r"(_p) : "memory"); \
    if (!_d) { \
        asm volatile("{\n\t.reg .pred P1;\n\t" \
            "WL_%=:\n\t" \
            "mbarrier.try_wait.parity.acquire.cta.shared::cta.b64 P1, [%0], %1, 0x989680;\n\t" \
            "@P1 bra.uni WD_%=;\n\t" \
            "bra.uni WL_%=;\n\t" \
            "WD_%=:\n\t}" :: "r"(_m), "r"(_p) : "memory"); \
    } \
} while (0)

__device__ __forceinline__ void bulk_g2s(uint32_t dst, const void* src, uint32_t bytes, uint32_t mbar) {
    asm volatile(
        "cp.async.bulk.shared::cluster.global.mbarrier::complete_tx::bytes [%0], [%1], %2, [%3];"
        :: "r"(dst), "l"(src), "r"(bytes), "r"(mbar) : "memory");
}

__device__ __forceinline__ void ldsm_x4(uint32_t& r0, uint32_t& r1, uint32_t& r2, uint32_t& r3,
                                        uint32_t addr) {
    asm volatile("ldmatrix.sync.aligned.m8n8.x4.shared.b16 {%0,%1,%2,%3}, [%4];"
        : "=r"(r0), "=r"(r1), "=r"(r2), "=r"(r3) : "r"(addr));
}

__device__ __forceinline__ void mma_bf16(float* c, uint32_t a0, uint32_t a1, uint32_t a2, uint32_t a3,
                                         uint32_t b0, uint32_t b1) {
    asm volatile(
        "mma.sync.aligned.m16n8k16.row.col.f32.bf16.bf16.f32 "
        "{%0,%1,%2,%3}, {%4,%5,%6,%7}, {%8,%9}, {%0,%1,%2,%3};"
        : "+f"(c[0]), "+f"(c[1]), "+f"(c[2]), "+f"(c[3])
        : "r"(a0), "r"(a1), "r"(a2), "r"(a3), "r"(b0), "r"(b1));
}

__device__ __forceinline__ uint32_t pack_bf16(float lo, float hi) {
    uint32_t r;
    asm("cvt.rn.bf16x2.f32 %0, %1, %2;" : "=r"(r) : "f"(hi), "f"(lo));
    return r;
}

// ---------------------------------------------------------------------------
// Prep: [0,1024) G->bf16 swz; [1024,2048) Q->bf16*log2e swz; [2048,3072) diag
// ---------------------------------------------------------------------------
__global__ void prep_kernel(const float* __restrict__ q, const float* __restrict__ g) {
    if (blockIdx.x < 2048) {
        bool isQ = blockIdx.x >= 1024;
        const float* src = isQ ? q : g;
        unsigned char* dst = isQ ? q_swz : g_swz;
        float scale = isQ ? LOG2E : 1.0f;
        int idx = (blockIdx.x & 1023) * 256 + threadIdx.x;   // 16B bf16 chunk (8 floats)
        int j = idx >> 5;          // row
        int c = idx & 31;          // chunk16 within row
        const float4* s4 = reinterpret_cast<const float4*>(src);
        float4 v0 = s4[j * 64 + c * 2];
        float4 v1 = s4[j * 64 + c * 2 + 1];
        uint4 u;
        u.x = pack_bf16(v0.x * scale, v0.y * scale);
        u.y = pack_bf16(v0.z * scale, v0.w * scale);
        u.z = pack_bf16(v1.x * scale, v1.y * scale);
        u.w = pack_bf16(v1.z * scale, v1.w * scale);
        int blk = j >> 6, r = j & 63;   // 64-row blocks
        *reinterpret_cast<uint4*>(dst + (size_t)blk * TILE_BYTES + r * ROWB +
                                  ((c ^ (r & 7)) << 4)) = u;
    } else {
        int w = threadIdx.x >> 5, lane = threadIdx.x & 31;
        int row = (blockIdx.x - 2048) * 8 + w;
        const float4* qr = reinterpret_cast<const float4*>(q + (size_t)row * DDIM);
        const float4* gr = reinterpret_cast<const float4*>(g + (size_t)row * DDIM);
        float acc = 0.f;
#pragma unroll
        for (int i = 0; i < 2; i++) {
            float4 a = qr[i * 32 + lane];
            float4 b = gr[i * 32 + lane];
            acc += a.x * b.x + a.y * b.y + a.z * b.z + a.w * b.w;
        }
#pragma unroll
        for (int o = 16; o; o >>= 1) acc += __shfl_xor_sync(0xffffffffu, acc, o);
        if (lane == 0) g_diag_arr[row] = acc * LOG2E;
    }
}

// ---------------------------------------------------------------------------
// Main fused kernel: R3 pipelined structure + bulk A + no-max epilogue
// ---------------------------------------------------------------------------
__global__ void __launch_bounds__(256, 1)
fused_kernel(float* __restrict__ out) {
    extern __shared__ char smem[];
    const uint32_t sb = smem_to_u32(smem);
    const int tid  = threadIdx.x;
    const int wid  = tid >> 5;
    const int lane = tid & 31;
    const int rb    = blockIdx.x >> 4;    // row block (0..63)
    const int chunk = blockIdx.x & 15;    // column chunk (0..15)
    const int ct0   = chunk * NTU;
    const uint32_t mbarA = sb + SM_MBAR + NBUF * 8;

    if (tid == 0) {
#pragma unroll
        for (int i = 0; i <= NBUF; i++) MBARRIER_INIT(sb + SM_MBAR + i * 8, 1);
    }
    asm volatile("fence.proxy.async.shared::cta;" ::: "memory");
    __syncthreads();

    if (tid == 0) {
        MBARRIER_EXPECT_TX(mbarA, A_BYTES);
        bulk_g2s(sb + SM_A, q_swz + (size_t)rb * A_BYTES, A_BYTES, mbarA);
#pragma unroll
        for (int p = 0; p < NBUF; p++) {
            MBARRIER_EXPECT_TX(sb + SM_MBAR + p * 8, TILE_BYTES);
            bulk_g2s(sb + SM_G + p * TILE_BYTES,
                     g_swz + (size_t)(ct0 + p) * TILE_BYTES,
                     TILE_BYTES, sb + SM_MBAR + p * 8);
        }
    }

    // ---- per-lane addressing ----
    const int g_row = lane >> 2;
    const uint32_t a_row  = wid * 16 + ((lane >> 3) & 1) * 8 + (lane & 7);
    const uint32_t a_base = sb + SM_A + a_row * ROWB;
    const uint32_t a_x    = a_row & 7;
    const uint32_t a_hi   = lane >> 4;
    const uint32_t b_rowl = ((lane >> 4) << 3) + (lane & 7);
    const uint32_t b_x    = b_rowl & 7;
    const uint32_t b_hi   = (lane >> 3) & 1;
    const uint32_t b_roff = b_rowl * ROWB;

    float sA = 0.f, sB = 0.f;

    MBARRIER_WAIT_PARITY(mbarA, 0);   // A resident

    auto do_tile = [&](int t, float (&acc)[32]) {
        const int b = t & (NBUF - 1);
        const uint32_t mb = sb + SM_MBAR + b * 8;
        MBARRIER_WAIT_PARITY(mb, (t >> 2) & 1);
#pragma unroll
        for (int i = 0; i < 32; i++) acc[i] = 0.f;
        const uint32_t gbase = sb + SM_G + b * TILE_BYTES + b_roff;
#pragma unroll
        for (int ks = 0; ks < 16; ks++) {
            uint32_t a0, a1, a2, a3;
            ldsm_x4(a0, a1, a2, a3, a_base + ((((ks << 1) + a_hi) ^ a_x) << 4));
            const uint32_t bc = (((ks << 1) + b_hi) ^ b_x) << 4;
#pragma unroll
            for (int nb = 0; nb < 4; nb++) {
                uint32_t b0, b1, b2, b3;
                ldsm_x4(b0, b1, b2, b3, gbase + nb * (16 * ROWB) + bc);
                mma_bf16(acc + nb * 8 + 0, a0, a1, a2, a3, b0, b1);
                mma_bf16(acc + nb * 8 + 4, a0, a1, a2, a3, b2, b3);
            }
        }
        __syncthreads();   // all warps done reading buf b
        if (tid == 0 && t + NBUF < NTU) {
            MBARRIER_EXPECT_TX(mb, TILE_BYTES);
            bulk_g2s(sb + SM_G + b * TILE_BYTES,
                     g_swz + (size_t)(ct0 + t + NBUF) * TILE_BYTES,
                     TILE_BYTES, mb);
        }
    };

    auto do_epi = [&](float (&acc)[32]) {
        float t0 = 0.f, t1 = 0.f;
#pragma unroll
        for (int i = 0; i < 8; i++) {
            t0 += ex2(acc[i * 4 + 0]) + ex2(acc[i * 4 + 1]);
            t1 += ex2(acc[i * 4 + 2]) + ex2(acc[i * 4 + 3]);
        }
        sA += t0; sB += t1;
    };

    // ---- software-pipelined main loop: epilogue(t-1) overlaps MMA(t) ----
    float accA[32], accB[32];
    do_tile(0, accA);
    for (int tt = 1; tt < NTU; tt += 2) {
        do_tile(tt, accB);
        do_epi(accA);
        if (tt + 1 < NTU) {
            do_tile(tt + 1, accA);
            do_epi(accB);
        }
    }
    do_epi(accB);   // NTU even: last tile landed in accB

    // ---- quad reduce + write partial sums ----
    sA += __shfl_xor_sync(0xffffffffu, sA, 1);
    sA += __shfl_xor_sync(0xffffffffu, sA, 2);
    sB += __shfl_xor_sync(0xffffffffu, sB, 1);
    sB += __shfl_xor_sync(0xffffffffu, sB, 2);
    if ((lane & 3) == 0) {
        int r0 = rb * BM + wid * 16 + g_row;
        g_ps[chunk * NROWS + r0] = sA;
        g_ps[chunk * NROWS + r0 + 8] = sB;
    }

    // ---- last-CTA finalize ----
    __shared__ unsigned s_last;
    __shared__ float red[256];
    __threadfence();
    __syncthreads();
    if (tid == 0) {
        unsigned old = atomicAdd(&g_cnt, 1u);
        s_last = (old == GRID_F - 1) ? 1u : 0u;
        if (s_last) g_cnt = 0;   // reset for next replay
    }
    __syncthreads();
    if (!s_last) return;
    __threadfence();

    float acc2 = 0.f;
    for (int i = tid; i < NROWS; i += 256) {
        float S = 0.f;
#pragma unroll
        for (int c = 0; c < NCHUNK; c++) S += g_ps[c * NROWS + i];
        float p = ex2(g_diag_arr[i]) / S;
        acc2 += -logf(p + 1e-5f);
    }
    red[tid] = acc2;
    __syncthreads();
    for (int o = 128; o; o >>= 1) {
        if (tid < o) red[tid] += red[tid + o];
        __syncthreads();
    }
    if (tid == 0) out[0] = red[0] / (float)NROWS;
}

// ---------------------------------------------------------------------------
// Launch
// ---------------------------------------------------------------------------
extern "C" void kernel_launch(void* const* d_in, const int* in_sizes, int n_in,
                              void* d_out, int out_size) {
    (void)in_sizes; (void)n_in; (void)out_size;
    const float* q = (const float*)d_in[0];
    const float* g = (const float*)d_in[1];
    float* out = (float*)d_out;

    cudaFuncSetAttribute(fused_kernel, cudaFuncAttributeMaxDynamicSharedMemorySize, SMEM_TOTAL);

    prep_kernel<<<3072, 256>>>(q, g);
    fused_kernel<<<GRID_F, 256, SMEM_TOTAL>>>(out);
}

// round 6
// speedup vs baseline: 1.5748x; 1.0618x over previous
#include <cuda_runtime.h>
#include <cuda_bf16.h>
#include <cstdint>

// ---------------------------------------------------------------------------
// Constants
// ---------------------------------------------------------------------------
constexpr int NROWS = 8192;
constexpr int DDIM  = 256;
constexpr int BM    = 128;            // Q rows per CTA
constexpr int BN    = 64;             // G rows per tile
constexpr int NTU   = 8;              // tiles per CTA (unit)
constexpr int NCHUNK = NROWS / (BN * NTU);    // 16 column chunks
constexpr int GRID_F = (NROWS / BM) * NCHUNK; // 1024 CTAs
constexpr int NPS   = NCHUNK * 2;             // 32 partial slots (chunk x n-half)
constexpr int ROWB  = DDIM * 2;       // 512 bytes per bf16 row
constexpr int TILE_BYTES = BN * ROWB; // 32768
constexpr int A_BYTES = BM * ROWB;    // 65536
constexpr int NBUF  = 4;

constexpr int SM_A    = 0;
constexpr int SM_G    = A_BYTES;                     // 65536
constexpr int SM_MBAR = SM_G + NBUF * TILE_BYTES;    // 196608
constexpr int SMEM_TOTAL = SM_MBAR + 64;

#define LOG2E 1.4426950408889634f

// ---------------------------------------------------------------------------
// Device scratch
// ---------------------------------------------------------------------------
__device__ __align__(128) unsigned char g_swz[NROWS * ROWB];  // 4 MB G bf16 (swizzled)
__device__ __align__(128) unsigned char q_swz[NROWS * ROWB];  // 4 MB Q bf16*log2e (swizzled)
__device__ float g_diag_arr[NROWS];                           // diag * log2e
__device__ float g_ps[NPS * NROWS];                           // 1 MB partial sums
__device__ unsigned g_cnt = 0;

// ---------------------------------------------------------------------------
// PTX helpers (sm_103 baseline only)
// ---------------------------------------------------------------------------
__device__ __forceinline__ uint32_t smem_to_u32(const void* p) {
    uint32_t a;
    asm("{ .reg .u64 t; cvta.to.shared.u64 t, %1; cvt.u32.u64 %0, t; }" : "=r"(a) : "l"(p));
    return a;
}

__device__ __forceinline__ float ex2(float x) {
    float r;
    asm("ex2.approx.f32 %0, %1;" : "=f"(r) : "f"(x));
    return r;
}

#define MBARRIER_INIT(addr, count) \
    asm volatile("mbarrier.init.shared.b64 [%0], %1;" :: "r"((uint32_t)(addr)), "r"((uint32_t)(count)) : "memory")

#define MBARRIER_EXPECT_TX(addr, tx) \
    asm volatile("mbarrier.arrive.expect_tx.shared.b64 _, [%0], %1;" :: "r"((uint32_t)(addr)), "r"((uint32_t)(tx)) : "memory")

#define MBARRIER_WAIT_PARITY(addr, ph) do { \
    uint32_t _m = (uint32_t)(addr), _p = (uint32_t)(ph), _d; \
    asm volatile("{\n\t.reg .pred p;\n\t" \
        "mbarrier.try_wait.parity.acquire.cta.shared::cta.b64 p, [%1], %2;\n\t" \
        "selp.b32 %0, 1, 0, p;\n\t}" : "=r"(_d) : "r"(_m), "r"(_p) : "memory"); \
    if (!_d) { \
        asm volatile("{\n\t.reg .pred P1;\n\t" \
            "WL_%=:\n\t" \
            "mbarrier.try_wait.parity.acquire.cta.shared::cta.b64 P1, [%0], %1, 0x989680;\n\t" \
            "@P1 bra.uni WD_%=;\n\t" \
            "bra.uni WL_%=;\n\t" \
            "WD_%=:\n\t}" :: "r"(_m), "r"(_p) : "memory"); \
    } \
} while (0)

__device__ __forceinline__ void bulk_g2s(uint32_t dst, const void* src, uint32_t bytes, uint32_t mbar) {
    asm volatile(
        "cp.async.bulk.shared::cluster.global.mbarrier::complete_tx::bytes [%0], [%1], %2, [%3];"
        :: "r"(dst), "l"(src), "r"(bytes), "r"(mbar) : "memory");
}

__device__ __forceinline__ void ldsm_x4(uint32_t* r, uint32_t addr) {
    asm volatile("ldmatrix.sync.aligned.m8n8.x4.shared.b16 {%0,%1,%2,%3}, [%4];"
        : "=r"(r[0]), "=r"(r[1]), "=r"(r[2]), "=r"(r[3]) : "r"(addr));
}

__device__ __forceinline__ void mma_bf16(float* c, const uint32_t* a, uint32_t b0, uint32_t b1) {
    asm volatile(
        "mma.sync.aligned.m16n8k16.row.col.f32.bf16.bf16.f32 "
        "{%0,%1,%2,%3}, {%4,%5,%6,%7}, {%8,%9}, {%0,%1,%2,%3};"
        : "+f"(c[0]), "+f"(c[1]), "+f"(c[2]), "+f"(c[3])
        : "r"(a[0]), "r"(a[1]), "r"(a[2]), "r"(a[3]), "r"(b0), "r"(b1));
}

__device__ __forceinline__ uint32_t pack_bf16(float lo, float hi) {
    uint32_t r;
    asm("cvt.rn.bf16x2.f32 %0, %1, %2;" : "=r"(r) : "f"(hi), "f"(lo));
    return r;
}

// ---------------------------------------------------------------------------
// Prep: [0,1024) G->bf16 swz; [1024,2048) Q->bf16*log2e swz; [2048,3072) diag
// ---------------------------------------------------------------------------
__global__ void prep_kernel(const float* __restrict__ q, const float* __restrict__ g) {
    if (blockIdx.x < 2048) {
        bool isQ = blockIdx.x >= 1024;
        const float* src = isQ ? q : g;
        unsigned char* dst = isQ ? q_swz : g_swz;
        float scale = isQ ? LOG2E : 1.0f;
        int idx = (blockIdx.x & 1023) * 256 + threadIdx.x;
        int j = idx >> 5;
        int c = idx & 31;
        const float4* s4 = reinterpret_cast<const float4*>(src);
        float4 v0 = s4[j * 64 + c * 2];
        float4 v1 = s4[j * 64 + c * 2 + 1];
        uint4 u;
        u.x = pack_bf16(v0.x * scale, v0.y * scale);
        u.y = pack_bf16(v0.z * scale, v0.w * scale);
        u.z = pack_bf16(v1.x * scale, v1.y * scale);
        u.w = pack_bf16(v1.z * scale, v1.w * scale);
        int blk = j >> 6, r = j & 63;
        *reinterpret_cast<uint4*>(dst + (size_t)blk * TILE_BYTES + r * ROWB +
                                  ((c ^ (r & 7)) << 4)) = u;
    } else {
        int w = threadIdx.x >> 5, lane = threadIdx.x & 31;
        int row = (blockIdx.x - 2048) * 8 + w;
        const float4* qr = reinterpret_cast<const float4*>(q + (size_t)row * DDIM);
        const float4* gr = reinterpret_cast<const float4*>(g + (size_t)row * DDIM);
        float acc = 0.f;
#pragma unroll
        for (int i = 0; i < 2; i++) {
            float4 a = qr[i * 32 + lane];
            float4 b = gr[i * 32 + lane];
            acc += a.x * b.x + a.y * b.y + a.z * b.z + a.w * b.w;
        }
#pragma unroll
        for (int o = 16; o; o >>= 1) acc += __shfl_xor_sync(0xffffffffu, acc, o);
        if (lane == 0) g_diag_arr[row] = acc * LOG2E;
    }
}

// ---------------------------------------------------------------------------
// Main fused kernel: 32x32 warp tiles + k-step ldsm prefetch + epi overlap
// ---------------------------------------------------------------------------
__global__ void __launch_bounds__(256, 1)
fused_kernel(float* __restrict__ out) {
    extern __shared__ char smem[];
    const uint32_t sb = smem_to_u32(smem);
    const int tid  = threadIdx.x;
    const int wid  = tid >> 5;
    const int lane = tid & 31;
    const int m_pos = wid & 3;            // warp row quadrant (32 rows)
    const int n_pos = wid >> 2;           // warp col half (32 of 64)
    const int rb    = blockIdx.x >> 4;
    const int chunk = blockIdx.x & 15;
    const int ct0   = chunk * NTU;
    const uint32_t mbarA = sb + SM_MBAR + NBUF * 8;

    if (tid == 0) {
#pragma unroll
        for (int i = 0; i <= NBUF; i++) MBARRIER_INIT(sb + SM_MBAR + i * 8, 1);
    }
    asm volatile("fence.proxy.async.shared::cta;" ::: "memory");
    __syncthreads();

    if (tid == 0) {
        MBARRIER_EXPECT_TX(mbarA, A_BYTES);
        bulk_g2s(sb + SM_A, q_swz + (size_t)rb * A_BYTES, A_BYTES, mbarA);
#pragma unroll
        for (int p = 0; p < NBUF; p++) {
            MBARRIER_EXPECT_TX(sb + SM_MBAR + p * 8, TILE_BYTES);
            bulk_g2s(sb + SM_G + p * TILE_BYTES,
                     g_swz + (size_t)(ct0 + p) * TILE_BYTES,
                     TILE_BYTES, sb + SM_MBAR + p * 8);
        }
    }

    // ---- per-lane addressing ----
    // A: two 16-row fragments at rows m_pos*32 and m_pos*32+16
    const uint32_t a_rowl = ((lane >> 3) & 1) * 8 + (lane & 7);
    const uint32_t a_x    = a_rowl & 7;
    const uint32_t a_hi   = lane >> 4;
    const uint32_t a_base0 = sb + SM_A + (m_pos * 32 + a_rowl) * ROWB;
    const uint32_t a_base1 = a_base0 + 16 * ROWB;
    // B: two 16-col fragments at n = n_pos*32 and n_pos*32+16
    const uint32_t b_rowl = ((lane >> 4) << 3) + (lane & 7);
    const uint32_t b_x    = b_rowl & 7;
    const uint32_t b_hi   = (lane >> 3) & 1;
    const uint32_t b_off0 = (n_pos * 32 + b_rowl) * ROWB;
    const uint32_t b_off1 = b_off0 + 16 * ROWB;

    float sums[4] = {0.f, 0.f, 0.f, 0.f};

    MBARRIER_WAIT_PARITY(mbarA, 0);   // A resident

    auto do_tile = [&](int t, float (&acc)[32]) {
        const int b = t & (NBUF - 1);
        const uint32_t mb = sb + SM_MBAR + b * 8;
        MBARRIER_WAIT_PARITY(mb, (t >> 2) & 1);
#pragma unroll
        for (int i = 0; i < 32; i++) acc[i] = 0.f;
        const uint32_t gbase = sb + SM_G + b * TILE_BYTES;

        uint32_t aF[2][2][4], bF[2][2][4];   // [parity][frag][reg]
        // preload k-step 0
        ldsm_x4(aF[0][0], a_base0 + ((a_hi ^ a_x) << 4));
        ldsm_x4(aF[0][1], a_base1 + ((a_hi ^ a_x) << 4));
        ldsm_x4(bF[0][0], gbase + b_off0 + ((b_hi ^ b_x) << 4));
        ldsm_x4(bF[0][1], gbase + b_off1 + ((b_hi ^ b_x) << 4));
#pragma unroll
        for (int ks = 0; ks < 16; ks++) {
            const int cur = ks & 1, nxt = cur ^ 1;
            if (ks < 15) {   // prefetch k-step ks+1
                const uint32_t ac = ((((ks + 1) << 1) + a_hi) ^ a_x) << 4;
                const uint32_t bc = ((((ks + 1) << 1) + b_hi) ^ b_x) << 4;
                ldsm_x4(aF[nxt][0], a_base0 + ac);
                ldsm_x4(aF[nxt][1], a_base1 + ac);
                ldsm_x4(bF[nxt][0], gbase + b_off0 + bc);
                ldsm_x4(bF[nxt][1], gbase + b_off1 + bc);
            }
#pragma unroll
            for (int mb2 = 0; mb2 < 2; mb2++)
#pragma unroll
                for (int nb = 0; nb < 2; nb++) {
                    mma_bf16(acc + mb2 * 16 + nb * 8 + 0, aF[cur][mb2], bF[cur][nb][0], bF[cur][nb][1]);
                    mma_bf16(acc + mb2 * 16 + nb * 8 + 4, aF[cur][mb2], bF[cur][nb][2], bF[cur][nb][3]);
                }
        }
        __syncthreads();   // all warps done reading buf b
        if (tid == 0 && t + NBUF < NTU) {
            MBARRIER_EXPECT_TX(mb, TILE_BYTES);
            bulk_g2s(sb + SM_G + b * TILE_BYTES,
                     g_swz + (size_t)(ct0 + t + NBUF) * TILE_BYTES,
                     TILE_BYTES, mb);
        }
    };

    auto do_epi = [&](float (&acc)[32]) {
#pragma unroll
        for (int mb2 = 0; mb2 < 2; mb2++) {
            float t0 = 0.f, t1 = 0.f;
#pragma unroll
            for (int nb = 0; nb < 2; nb++) {
                const float* a4 = acc + mb2 * 16 + nb * 8;
                t0 += ex2(a4[0]) + ex2(a4[1]) + ex2(a4[4]) + ex2(a4[5]);
                t1 += ex2(a4[2]) + ex2(a4[3]) + ex2(a4[6]) + ex2(a4[7]);
            }
            sums[mb2 * 2 + 0] += t0;
            sums[mb2 * 2 + 1] += t1;
        }
    };

    // ---- software-pipelined main loop ----
    float accA[32], accB[32];
    do_tile(0, accA);
    for (int tt = 1; tt < NTU; tt += 2) {
        do_tile(tt, accB);
        do_epi(accA);
        if (tt + 1 < NTU) {
            do_tile(tt + 1, accA);
            do_epi(accB);
        }
    }
    do_epi(accB);

    // ---- quad reduce (lanes sharing a row) + write partials ----
#pragma unroll
    for (int i = 0; i < 4; i++) {
        sums[i] += __shfl_xor_sync(0xffffffffu, sums[i], 1);
        sums[i] += __shfl_xor_sync(0xffffffffu, sums[i], 2);
    }
    if ((lane & 3) == 0) {
        const int row0 = rb * BM + m_pos * 32 + (lane >> 2);
        const size_t base = (size_t)(chunk * 2 + n_pos) * NROWS;
        g_ps[base + row0]      = sums[0];
        g_ps[base + row0 + 8]  = sums[1];
        g_ps[base + row0 + 16] = sums[2];
        g_ps[base + row0 + 24] = sums[3];
    }

    // ---- last-CTA finalize ----
    __shared__ unsigned s_last;
    __shared__ float red[256];
    __threadfence();
    __syncthreads();
    if (tid == 0) {
        unsigned old = atomicAdd(&g_cnt, 1u);
        s_last = (old == GRID_F - 1) ? 1u : 0u;
        if (s_last) g_cnt = 0;
    }
    __syncthreads();
    if (!s_last) return;
    __threadfence();

    float acc2 = 0.f;
    for (int i = tid; i < NROWS; i += 256) {
        float S = 0.f;
#pragma unroll
        for (int c = 0; c < NPS; c++) S += g_ps[(size_t)c * NROWS + i];
        float p = ex2(g_diag_arr[i]) / S;
        acc2 += -logf(p + 1e-5f);
    }
    red[tid] = acc2;
    __syncthreads();
    for (int o = 128; o; o >>= 1) {
        if (tid < o) red[tid] += red[tid + o];
        __syncthreads();
    }
    if (tid == 0) out[0] = red[0] / (float)NROWS;
}

// ---------------------------------------------------------------------------
// Launch
// ---------------------------------------------------------------------------
extern "C" void kernel_launch(void* const* d_in, const int* in_sizes, int n_in,
                              void* d_out, int out_size) {
    (void)in_sizes; (void)n_in; (void)out_size;
    const float* q = (const float*)d_in[0];
    const float* g = (const float*)d_in[1];
    float* out = (float*)d_out;

    cudaFuncSetAttribute(fused_kernel, cudaFuncAttributeMaxDynamicSharedMemorySize, SMEM_TOTAL);

    prep_kernel<<<3072, 256>>>(q, g);
    fused_kernel<<<GRID_F, 256, SMEM_TOTAL>>>(out);
}